// round 12
// baseline (speedup 1.0000x reference)
#include <cuda_runtime.h>
#include <cstdint>
#include <math.h>

#define N_ELEM 256
#define T_SEQ  32
#define H_DIM  512
#define MAXS   (N_ELEM * T_SEQ)          // worst-case executed rounds
#define NCTA_G 64                        // CTAs per layer group
#define CANARY 0x7F123456u               // NaN payload; |h|<=1 so bit-pattern unreachable

// Write-once broadcast slots (u32 bit patterns; avoids NaN canonicalization concerns)
__device__ unsigned g_h0[(size_t)MAXS * H_DIM];
__device__ unsigned g_h1[(size_t)MAXS * H_DIM];
__device__ unsigned g_abort;             // watchdog abort flag

__device__ __forceinline__ uint2 ldcg2u(const unsigned* p) {
    uint2 v;
    asm volatile("ld.global.cg.v2.u32 {%0,%1}, [%2];"
                 : "=r"(v.x), "=r"(v.y) : "l"(p) : "memory");
    return v;
}
__device__ __forceinline__ void stcg1u(unsigned* p, unsigned v) {
    asm volatile("st.global.cg.u32 [%0], %1;" :: "l"(p), "r"(v) : "memory");
}
__device__ __forceinline__ unsigned ldcg1u(const unsigned* p) {
    unsigned v;
    asm volatile("ld.global.cg.u32 %0, [%1];" : "=r"(v) : "l"(p) : "memory");
    return v;
}

// Warp-collective: poll ONE disjoint 64-float slice (2 floats/lane) until no lane
// sees the canary, then deposit the slice into smem. Detect+data = one L2 RTT.
__device__ __forceinline__ void poll_slice1(const unsigned* g, float* sh, int lane) {
    const unsigned* p = g + lane * 2;
    unsigned it = 0;
    for (;;) {
        uint2 a = ldcg2u(p);
        bool ok = (a.x != CANARY) & (a.y != CANARY);
        if (__all_sync(0xffffffffu, (int)ok)) {
            sh[lane * 2]     = __uint_as_float(a.x);
            sh[lane * 2 + 1] = __uint_as_float(a.y);
            return;
        }
        if ((++it & 1023u) == 0u) {
            if (ldcg1u(&g_abort) != 0u) { sh[lane * 2] = 0.f; sh[lane * 2 + 1] = 0.f; return; }
            if (it >= (1u << 22)) stcg1u(&g_abort, 1u);
        }
    }
}
// Joint variant: poll two slices (one from each of two vectors) in one loop.
__device__ __forceinline__ void poll_slice2(const unsigned* g1, const unsigned* g2,
                                            float* sh1, float* sh2, int lane) {
    const unsigned* p1 = g1 + lane * 2;
    const unsigned* p2 = g2 + lane * 2;
    unsigned it = 0;
    for (;;) {
        uint2 a = ldcg2u(p1);
        uint2 b = ldcg2u(p2);
        bool ok = (a.x != CANARY) & (a.y != CANARY) & (b.x != CANARY) & (b.y != CANARY);
        if (__all_sync(0xffffffffu, (int)ok)) {
            sh1[lane * 2]     = __uint_as_float(a.x);
            sh1[lane * 2 + 1] = __uint_as_float(a.y);
            sh2[lane * 2]     = __uint_as_float(b.x);
            sh2[lane * 2 + 1] = __uint_as_float(b.y);
            return;
        }
        if ((++it & 1023u) == 0u) {
            if (ldcg1u(&g_abort) != 0u) {
                sh1[lane * 2] = sh1[lane * 2 + 1] = 0.f;
                sh2[lane * 2] = sh2[lane * 2 + 1] = 0.f;
                return;
            }
            if (it >= (1u << 22)) stcg1u(&g_abort, 1u);
        }
    }
}
// Four independent warp sums, butterfly levels interleaved so the four
// 26-cycle shuffle chains pipeline instead of serializing.
__device__ __forceinline__ void wsum4(float& a, float& b, float& c, float& d) {
#pragma unroll
    for (int m = 16; m >= 1; m >>= 1) {
        a += __shfl_xor_sync(0xffffffffu, a, m);
        b += __shfl_xor_sync(0xffffffffu, b, m);
        c += __shfl_xor_sync(0xffffffffu, c, m);
        d += __shfl_xor_sync(0xffffffffu, d, m);
    }
}
__device__ __forceinline__ float dot4(float4 a, float4 b) {
    return a.x * b.x + a.y * b.y + a.z * b.z + a.w * b.w;
}
// Fast sigmoid/tanh via EX2-class approx ops (~1e-6 rel err).
__device__ __forceinline__ float fsigmoid(float v) {
    return __fdividef(1.0f, 1.0f + __expf(-v));
}
__device__ __forceinline__ float ftanh(float v) {
    return 1.0f - __fdividef(2.0f, __expf(2.0f * v) + 1.0f);
}

// Canary-fill both slot arrays; reset abort; optionally write dates (as float).
__global__ void init_kernel(const int* __restrict__ dates, float* __restrict__ out,
                            int write_dates) {
    size_t idx = (size_t)blockIdx.x * blockDim.x + threadIdx.x;
    size_t n4 = (size_t)MAXS * H_DIM / 4;
    uint4 cv = make_uint4(CANARY, CANARY, CANARY, CANARY);
    if (idx < n4) {
        reinterpret_cast<uint4*>(g_h0)[idx] = cv;
        reinterpret_cast<uint4*>(g_h1)[idx] = cv;
    }
    if (idx == 0) g_abort = 0u;
    if (write_dates && idx < N_ELEM) out[idx] = (float)dates[idx];
}

// Persistent 2-layer pipelined GRU: sliced canary protocol + smem redistribution,
// interleaved shfl reductions, fast gate math on all lanes.
// CTAs 0..63   = group A (layer 0): x-projection + recurrence, emits h0[s].
// CTAs 64..127 = group B (layer 1): consumes h0[s], own recurrence, emits h1[s]+states.
__global__ void __launch_bounds__(256, 1)
gru_persistent(const int* __restrict__ dates, const float* __restrict__ x,
               const float* __restrict__ Wih0, const float* __restrict__ Whh0,
               const float* __restrict__ bih0, const float* __restrict__ bhh0,
               const float* __restrict__ Wih1, const float* __restrict__ Whh1,
               const float* __restrict__ bih1, const float* __restrict__ bhh1,
               float* __restrict__ out_states) {
    __shared__ int sdates[N_ELEM];
    __shared__ __align__(16) float sh_prev[2][H_DIM];   // myH[s-1]
    __shared__ __align__(16) float sh_x[2][H_DIM];      // B only: h0[s]
    int tid = threadIdx.x;
    if (tid < N_ELEM) sdates[tid] = dates[tid];
    __syncthreads();

    int warp = tid >> 5, lane = tid & 31;
    bool isB = (blockIdx.x >= NCTA_G);
    int cta  = isB ? (blockIdx.x - NCTA_G) : blockIdx.x;
    int c    = cta * 8 + warp;                    // owned output channel, 0..511
    int slice = warp * 64;                        // this warp's polled slice base

    const float* Wi = isB ? Wih1 : Wih0;
    const float* Wh = isB ? Whh1 : Whh0;
    const float* bi = isB ? bih1 : bih0;
    const float* bh = isB ? bhh1 : bhh0;

    // Register-resident weights: 3 gate rows (r,z,n) x 16 k-values for both matmuls.
    float4 wi[3][4], wh[3][4];
#pragma unroll
    for (int g = 0; g < 3; g++) {
        const float4* pi = reinterpret_cast<const float4*>(
            Wi + (size_t)(g * H_DIM + c) * H_DIM + lane * 16);
        const float4* ph = reinterpret_cast<const float4*>(
            Wh + (size_t)(g * H_DIM + c) * H_DIM + lane * 16);
#pragma unroll
        for (int j = 0; j < 4; j++) { wi[g][j] = pi[j]; wh[g][j] = ph[j]; }
    }
    float b_r  = bi[c] + bh[c];
    float b_z  = bi[H_DIM + c] + bh[H_DIM + c];
    float b_in = bi[2 * H_DIM + c];
    float b_hn = bh[2 * H_DIM + c];
    float hcur = 0.0f;

    unsigned* myH = isB ? g_h1 : g_h0;

    int s = 0;                                    // global executed-round index
    for (int n = 0; n < N_ELEM; n++) {
        bool run = (n == 0) || (sdates[n] != sdates[n - 1]);
        if (!run) {
            if (isB && lane == 0) out_states[(size_t)n * H_DIM + c] = hcur;
            continue;
        }
        for (int t = 0; t < T_SEQ; t++, s++) {
            int par = s & 1;
            // Two accumulators per sum -> halved FFMA dependency chains.
            float gr0 = 0.f, gr1 = 0.f, gz0 = 0.f, gz1 = 0.f, gn0 = 0.f, gn1 = 0.f;

            // Group A: x-side projection first (off the detect path).
            if (!isB) {
                float4 xv[4];
                const float4* xp = reinterpret_cast<const float4*>(
                    x + ((size_t)n * T_SEQ + t) * H_DIM + lane * 16);
#pragma unroll
                for (int j = 0; j < 4; j++) xv[j] = xp[j];
                gr0 = dot4(wi[0][0], xv[0]); gr1 = dot4(wi[0][1], xv[1]);
                gr0 += dot4(wi[0][2], xv[2]); gr1 += dot4(wi[0][3], xv[3]);
                gz0 = dot4(wi[1][0], xv[0]); gz1 = dot4(wi[1][1], xv[1]);
                gz0 += dot4(wi[1][2], xv[2]); gz1 += dot4(wi[1][3], xv[3]);
                gn0 = dot4(wi[2][0], xv[0]); gn1 = dot4(wi[2][1], xv[1]);
                gn0 += dot4(wi[2][2], xv[2]); gn1 += dot4(wi[2][3], xv[3]);
            }

            // ---- sliced canary poll (detect + data in ONE L2 RTT) ----
            if (!isB) {
                if (s > 0)
                    poll_slice1(g_h0 + (size_t)(s - 1) * H_DIM + slice,
                                &sh_prev[par][slice], lane);
            } else {
                if (s > 0)
                    poll_slice2(g_h1 + (size_t)(s - 1) * H_DIM + slice,
                                g_h0 + (size_t)s * H_DIM + slice,
                                &sh_prev[par][slice], &sh_x[par][slice], lane);
                else
                    poll_slice1(g_h0 + (size_t)s * H_DIM + slice,
                                &sh_x[par][slice], lane);
            }
            __syncthreads();   // slices deposited; double-buffering: one bar per round

            // Group B: x-side projection from h0[s] (now in smem).
            if (isB) {
                float4 xv[4];
                const float4* xp = reinterpret_cast<const float4*>(&sh_x[par][0]) + lane * 4;
#pragma unroll
                for (int j = 0; j < 4; j++) xv[j] = xp[j];
                gr0 = dot4(wi[0][0], xv[0]); gr1 = dot4(wi[0][1], xv[1]);
                gr0 += dot4(wi[0][2], xv[2]); gr1 += dot4(wi[0][3], xv[3]);
                gz0 = dot4(wi[1][0], xv[0]); gz1 = dot4(wi[1][1], xv[1]);
                gz0 += dot4(wi[1][2], xv[2]); gz1 += dot4(wi[1][3], xv[3]);
                gn0 = dot4(wi[2][0], xv[0]); gn1 = dot4(wi[2][1], xv[1]);
                gn0 += dot4(wi[2][2], xv[2]); gn1 += dot4(wi[2][3], xv[3]);
            }
            // Recurrent-side projection from smem.
            float hr0 = 0.f, hr1 = 0.f, hz0 = 0.f, hz1 = 0.f, hn0 = 0.f, hn1 = 0.f;
            if (s > 0) {
                float4 hv[4];
                const float4* hp = reinterpret_cast<const float4*>(&sh_prev[par][0]) + lane * 4;
#pragma unroll
                for (int j = 0; j < 4; j++) hv[j] = hp[j];
                hr0 = dot4(wh[0][0], hv[0]); hr1 = dot4(wh[0][1], hv[1]);
                hr0 += dot4(wh[0][2], hv[2]); hr1 += dot4(wh[0][3], hv[3]);
                hz0 = dot4(wh[1][0], hv[0]); hz1 = dot4(wh[1][1], hv[1]);
                hz0 += dot4(wh[1][2], hv[2]); hz1 += dot4(wh[1][3], hv[3]);
                hn0 = dot4(wh[2][0], hv[0]); hn1 = dot4(wh[2][1], hv[1]);
                hn0 += dot4(wh[2][2], hv[2]); hn1 += dot4(wh[2][3], hv[3]);
            }

            // ---- interleaved warp reductions ----
            float ar  = (gr0 + gr1) + (hr0 + hr1);
            float az  = (gz0 + gz1) + (hz0 + hz1);
            float ani = gn0 + gn1;
            float anh = hn0 + hn1;
            wsum4(ar, az, ani, anh);

            // Gates on every lane (cheap; avoids lane0 serialization before store).
            float r  = fsigmoid(ar + b_r);
            float z  = fsigmoid(az + b_z);
            float nn = ftanh(ani + b_in + r * (anh + b_hn));
            hcur = (1.0f - z) * nn + z * hcur;
            if (lane == 0)
                stcg1u(myH + (size_t)s * H_DIM + c, __float_as_uint(hcur));
        }
        if (isB && lane == 0) out_states[(size_t)n * H_DIM + c] = hcur;
    }
}

extern "C" void kernel_launch(void* const* d_in, const int* in_sizes, int n_in,
                              void* d_out, int out_size) {
    const int*   dates = (const int*)d_in[0];
    const float* x     = (const float*)d_in[1];
    const float* Wih0  = (const float*)d_in[2];
    const float* Whh0  = (const float*)d_in[3];
    const float* bih0  = (const float*)d_in[4];
    const float* bhh0  = (const float*)d_in[5];
    const float* Wih1  = (const float*)d_in[6];
    const float* Whh1  = (const float*)d_in[7];
    const float* bih1  = (const float*)d_in[8];
    const float* bhh1  = (const float*)d_in[9];
    float* out = (float*)d_out;

    // Reference returns (dates, states); if out_size includes the extra N
    // elements, dates (cast to float) come first.
    int with_dates = (out_size >= N_ELEM + N_ELEM * H_DIM) ? 1 : 0;
    float* states = out + (with_dates ? N_ELEM : 0);

    size_t n4 = (size_t)MAXS * H_DIM / 4;        // uint4 count per array
    init_kernel<<<(int)((n4 + 255) / 256), 256>>>(dates, out, with_dates);
    gru_persistent<<<128, 256>>>(dates, x, Wih0, Whh0, bih0, bhh0,
                                 Wih1, Whh1, bih1, bhh1, states);
}

// round 13
// speedup vs baseline: 1.0223x; 1.0223x over previous
#include <cuda_runtime.h>
#include <cstdint>
#include <math.h>

#define N_ELEM 256
#define T_SEQ  32
#define H_DIM  512
#define MAXS   (N_ELEM * T_SEQ)          // worst-case executed rounds
#define NCTA_G 64                        // CTAs per layer group
#define CANARY 0x7F123456u               // NaN payload; |h|<=1 so bit-pattern unreachable
#define PROBE_GAP 220u                   // cycles between poll probes (rate cap)

// Write-once broadcast slots (u32 bit patterns; avoids NaN canonicalization concerns)
__device__ unsigned g_h0[(size_t)MAXS * H_DIM];
__device__ unsigned g_h1[(size_t)MAXS * H_DIM];
__device__ unsigned g_abort;             // watchdog abort flag

__device__ __forceinline__ uint2 ldcg2u(const unsigned* p) {
    uint2 v;
    asm volatile("ld.global.cg.v2.u32 {%0,%1}, [%2];"
                 : "=r"(v.x), "=r"(v.y) : "l"(p) : "memory");
    return v;
}
__device__ __forceinline__ void stcg1u(unsigned* p, unsigned v) {
    asm volatile("st.global.cg.u32 [%0], %1;" :: "l"(p), "r"(v) : "memory");
}
__device__ __forceinline__ unsigned ldcg1u(const unsigned* p) {
    unsigned v;
    asm volatile("ld.global.cg.u32 %0, [%1];" : "=r"(v) : "l"(p) : "memory");
    return v;
}
// Non-memory pause: caps poll request rate so LTS slice queues stay empty.
__device__ __forceinline__ void pause_cy(unsigned cycles) {
    unsigned long long t0 = clock64();
    while ((unsigned long long)(clock64() - t0) < cycles) { }
}

// Warp-collective: poll ONE disjoint 64-float slice (2 floats/lane) until no lane
// sees the canary, then deposit the slice into smem. First probe immediate; later
// probes rate-capped at one per PROBE_GAP cycles.
__device__ __forceinline__ void poll_slice1(const unsigned* g, float* sh, int lane) {
    const unsigned* p = g + lane * 2;
    unsigned it = 0;
    for (;;) {
        uint2 a = ldcg2u(p);
        bool ok = (a.x != CANARY) & (a.y != CANARY);
        if (__all_sync(0xffffffffu, (int)ok)) {
            sh[lane * 2]     = __uint_as_float(a.x);
            sh[lane * 2 + 1] = __uint_as_float(a.y);
            return;
        }
        pause_cy(PROBE_GAP);
        if ((++it & 255u) == 0u) {
            if (ldcg1u(&g_abort) != 0u) { sh[lane * 2] = 0.f; sh[lane * 2 + 1] = 0.f; return; }
            if (it >= (1u << 18)) stcg1u(&g_abort, 1u);
        }
    }
}
// Joint variant: poll two slices (one from each of two vectors) in one loop.
__device__ __forceinline__ void poll_slice2(const unsigned* g1, const unsigned* g2,
                                            float* sh1, float* sh2, int lane) {
    const unsigned* p1 = g1 + lane * 2;
    const unsigned* p2 = g2 + lane * 2;
    unsigned it = 0;
    for (;;) {
        uint2 a = ldcg2u(p1);
        uint2 b = ldcg2u(p2);
        bool ok = (a.x != CANARY) & (a.y != CANARY) & (b.x != CANARY) & (b.y != CANARY);
        if (__all_sync(0xffffffffu, (int)ok)) {
            sh1[lane * 2]     = __uint_as_float(a.x);
            sh1[lane * 2 + 1] = __uint_as_float(a.y);
            sh2[lane * 2]     = __uint_as_float(b.x);
            sh2[lane * 2 + 1] = __uint_as_float(b.y);
            return;
        }
        pause_cy(PROBE_GAP);
        if ((++it & 255u) == 0u) {
            if (ldcg1u(&g_abort) != 0u) {
                sh1[lane * 2] = sh1[lane * 2 + 1] = 0.f;
                sh2[lane * 2] = sh2[lane * 2 + 1] = 0.f;
                return;
            }
            if (it >= (1u << 18)) stcg1u(&g_abort, 1u);
        }
    }
}
// Four independent warp sums, butterfly levels interleaved so the four
// shuffle chains pipeline instead of serializing.
__device__ __forceinline__ void wsum4(float& a, float& b, float& c, float& d) {
#pragma unroll
    for (int m = 16; m >= 1; m >>= 1) {
        a += __shfl_xor_sync(0xffffffffu, a, m);
        b += __shfl_xor_sync(0xffffffffu, b, m);
        c += __shfl_xor_sync(0xffffffffu, c, m);
        d += __shfl_xor_sync(0xffffffffu, d, m);
    }
}
__device__ __forceinline__ float dot4(float4 a, float4 b) {
    return a.x * b.x + a.y * b.y + a.z * b.z + a.w * b.w;
}
// Fast sigmoid/tanh via EX2-class approx ops (~1e-6 rel err).
__device__ __forceinline__ float fsigmoid(float v) {
    return __fdividef(1.0f, 1.0f + __expf(-v));
}
__device__ __forceinline__ float ftanh(float v) {
    return 1.0f - __fdividef(2.0f, __expf(2.0f * v) + 1.0f);
}

// Canary-fill both slot arrays; reset abort; optionally write dates (as float).
__global__ void init_kernel(const int* __restrict__ dates, float* __restrict__ out,
                            int write_dates) {
    size_t idx = (size_t)blockIdx.x * blockDim.x + threadIdx.x;
    size_t n4 = (size_t)MAXS * H_DIM / 4;
    uint4 cv = make_uint4(CANARY, CANARY, CANARY, CANARY);
    if (idx < n4) {
        reinterpret_cast<uint4*>(g_h0)[idx] = cv;
        reinterpret_cast<uint4*>(g_h1)[idx] = cv;
    }
    if (idx == 0) g_abort = 0u;
    if (write_dates && idx < N_ELEM) out[idx] = (float)dates[idx];
}

// Persistent 2-layer pipelined GRU: sliced canary protocol + rate-capped polling,
// smem redistribution, interleaved shfl reductions, fast gate math.
// CTAs 0..63   = group A (layer 0): x-projection + recurrence, emits h0[s].
// CTAs 64..127 = group B (layer 1): consumes h0[s], own recurrence, emits h1[s]+states.
__global__ void __launch_bounds__(256, 1)
gru_persistent(const int* __restrict__ dates, const float* __restrict__ x,
               const float* __restrict__ Wih0, const float* __restrict__ Whh0,
               const float* __restrict__ bih0, const float* __restrict__ bhh0,
               const float* __restrict__ Wih1, const float* __restrict__ Whh1,
               const float* __restrict__ bih1, const float* __restrict__ bhh1,
               float* __restrict__ out_states) {
    __shared__ int sdates[N_ELEM];
    __shared__ __align__(16) float sh_prev[2][H_DIM];   // myH[s-1]
    __shared__ __align__(16) float sh_x[2][H_DIM];      // B only: h0[s]
    int tid = threadIdx.x;
    if (tid < N_ELEM) sdates[tid] = dates[tid];
    __syncthreads();

    int warp = tid >> 5, lane = tid & 31;
    bool isB = (blockIdx.x >= NCTA_G);
    int cta  = isB ? (blockIdx.x - NCTA_G) : blockIdx.x;
    int c    = cta * 8 + warp;                    // owned output channel, 0..511
    int slice = warp * 64;                        // this warp's polled slice base

    const float* Wi = isB ? Wih1 : Wih0;
    const float* Wh = isB ? Whh1 : Whh0;
    const float* bi = isB ? bih1 : bih0;
    const float* bh = isB ? bhh1 : bhh0;

    // Register-resident weights: 3 gate rows (r,z,n) x 16 k-values for both matmuls.
    float4 wi[3][4], wh[3][4];
#pragma unroll
    for (int g = 0; g < 3; g++) {
        const float4* pi = reinterpret_cast<const float4*>(
            Wi + (size_t)(g * H_DIM + c) * H_DIM + lane * 16);
        const float4* ph = reinterpret_cast<const float4*>(
            Wh + (size_t)(g * H_DIM + c) * H_DIM + lane * 16);
#pragma unroll
        for (int j = 0; j < 4; j++) { wi[g][j] = pi[j]; wh[g][j] = ph[j]; }
    }
    float b_r  = bi[c] + bh[c];
    float b_z  = bi[H_DIM + c] + bh[H_DIM + c];
    float b_in = bi[2 * H_DIM + c];
    float b_hn = bh[2 * H_DIM + c];
    float hcur = 0.0f;

    unsigned* myH = isB ? g_h1 : g_h0;

    int s = 0;                                    // global executed-round index
    for (int n = 0; n < N_ELEM; n++) {
        bool run = (n == 0) || (sdates[n] != sdates[n - 1]);
        if (!run) {
            if (isB && lane == 0) out_states[(size_t)n * H_DIM + c] = hcur;
            continue;
        }
        for (int t = 0; t < T_SEQ; t++, s++) {
            int par = s & 1;
            // Two accumulators per sum -> halved FFMA dependency chains.
            float gr0 = 0.f, gr1 = 0.f, gz0 = 0.f, gz1 = 0.f, gn0 = 0.f, gn1 = 0.f;

            // Group A: x-side projection first (off the detect path).
            if (!isB) {
                float4 xv[4];
                const float4* xp = reinterpret_cast<const float4*>(
                    x + ((size_t)n * T_SEQ + t) * H_DIM + lane * 16);
#pragma unroll
                for (int j = 0; j < 4; j++) xv[j] = xp[j];
                gr0 = dot4(wi[0][0], xv[0]); gr1 = dot4(wi[0][1], xv[1]);
                gr0 += dot4(wi[0][2], xv[2]); gr1 += dot4(wi[0][3], xv[3]);
                gz0 = dot4(wi[1][0], xv[0]); gz1 = dot4(wi[1][1], xv[1]);
                gz0 += dot4(wi[1][2], xv[2]); gz1 += dot4(wi[1][3], xv[3]);
                gn0 = dot4(wi[2][0], xv[0]); gn1 = dot4(wi[2][1], xv[1]);
                gn0 += dot4(wi[2][2], xv[2]); gn1 += dot4(wi[2][3], xv[3]);
            }

            // ---- sliced canary poll (detect + data in ONE L2 RTT, rate-capped) ----
            if (!isB) {
                if (s > 0)
                    poll_slice1(g_h0 + (size_t)(s - 1) * H_DIM + slice,
                                &sh_prev[par][slice], lane);
            } else {
                if (s > 0)
                    poll_slice2(g_h1 + (size_t)(s - 1) * H_DIM + slice,
                                g_h0 + (size_t)s * H_DIM + slice,
                                &sh_prev[par][slice], &sh_x[par][slice], lane);
                else
                    poll_slice1(g_h0 + (size_t)s * H_DIM + slice,
                                &sh_x[par][slice], lane);
            }
            __syncthreads();   // slices deposited; double-buffering: one bar per round

            // Group B: x-side projection from h0[s] (now in smem).
            if (isB) {
                float4 xv[4];
                const float4* xp = reinterpret_cast<const float4*>(&sh_x[par][0]) + lane * 4;
#pragma unroll
                for (int j = 0; j < 4; j++) xv[j] = xp[j];
                gr0 = dot4(wi[0][0], xv[0]); gr1 = dot4(wi[0][1], xv[1]);
                gr0 += dot4(wi[0][2], xv[2]); gr1 += dot4(wi[0][3], xv[3]);
                gz0 = dot4(wi[1][0], xv[0]); gz1 = dot4(wi[1][1], xv[1]);
                gz0 += dot4(wi[1][2], xv[2]); gz1 += dot4(wi[1][3], xv[3]);
                gn0 = dot4(wi[2][0], xv[0]); gn1 = dot4(wi[2][1], xv[1]);
                gn0 += dot4(wi[2][2], xv[2]); gn1 += dot4(wi[2][3], xv[3]);
            }
            // Recurrent-side projection from smem.
            float hr0 = 0.f, hr1 = 0.f, hz0 = 0.f, hz1 = 0.f, hn0 = 0.f, hn1 = 0.f;
            if (s > 0) {
                float4 hv[4];
                const float4* hp = reinterpret_cast<const float4*>(&sh_prev[par][0]) + lane * 4;
#pragma unroll
                for (int j = 0; j < 4; j++) hv[j] = hp[j];
                hr0 = dot4(wh[0][0], hv[0]); hr1 = dot4(wh[0][1], hv[1]);
                hr0 += dot4(wh[0][2], hv[2]); hr1 += dot4(wh[0][3], hv[3]);
                hz0 = dot4(wh[1][0], hv[0]); hz1 = dot4(wh[1][1], hv[1]);
                hz0 += dot4(wh[1][2], hv[2]); hz1 += dot4(wh[1][3], hv[3]);
                hn0 = dot4(wh[2][0], hv[0]); hn1 = dot4(wh[2][1], hv[1]);
                hn0 += dot4(wh[2][2], hv[2]); hn1 += dot4(wh[2][3], hv[3]);
            }

            // ---- interleaved warp reductions ----
            float ar  = (gr0 + gr1) + (hr0 + hr1);
            float az  = (gz0 + gz1) + (hz0 + hz1);
            float ani = gn0 + gn1;
            float anh = hn0 + hn1;
            wsum4(ar, az, ani, anh);

            // Gates on every lane (cheap; avoids lane0 serialization before store).
            float r  = fsigmoid(ar + b_r);
            float z  = fsigmoid(az + b_z);
            float nn = ftanh(ani + b_in + r * (anh + b_hn));
            hcur = (1.0f - z) * nn + z * hcur;
            if (lane == 0)
                stcg1u(myH + (size_t)s * H_DIM + c, __float_as_uint(hcur));
        }
        if (isB && lane == 0) out_states[(size_t)n * H_DIM + c] = hcur;
    }
}

extern "C" void kernel_launch(void* const* d_in, const int* in_sizes, int n_in,
                              void* d_out, int out_size) {
    const int*   dates = (const int*)d_in[0];
    const float* x     = (const float*)d_in[1];
    const float* Wih0  = (const float*)d_in[2];
    const float* Whh0  = (const float*)d_in[3];
    const float* bih0  = (const float*)d_in[4];
    const float* bhh0  = (const float*)d_in[5];
    const float* Wih1  = (const float*)d_in[6];
    const float* Whh1  = (const float*)d_in[7];
    const float* bih1  = (const float*)d_in[8];
    const float* bhh1  = (const float*)d_in[9];
    float* out = (float*)d_out;

    // Reference returns (dates, states); if out_size includes the extra N
    // elements, dates (cast to float) come first.
    int with_dates = (out_size >= N_ELEM + N_ELEM * H_DIM) ? 1 : 0;
    float* states = out + (with_dates ? N_ELEM : 0);

    size_t n4 = (size_t)MAXS * H_DIM / 4;        // uint4 count per array
    init_kernel<<<(int)((n4 + 255) / 256), 256>>>(dates, out, with_dates);
    gru_persistent<<<128, 256>>>(dates, x, Wih0, Whh0, bih0, bhh0,
                                 Wih1, Whh1, bih1, bhh1, states);
}